// round 1
// baseline (speedup 1.0000x reference)
#include <cuda_runtime.h>
#include <cuda_bf16.h>
#include <math.h>

#define B_SZ 2
#define S_LEN 2048
#define D_MODEL 2048
#define NH 16
#define NKVH 4
#define HD 128
#define MROWS (B_SZ*S_LEN)

// Scratch (allocation-free rule: __device__ globals)
__device__ float g_Q[(size_t)B_SZ*NH*S_LEN*HD];     // [b,h,s,d] post-rope
__device__ float g_K[(size_t)B_SZ*NKVH*S_LEN*HD];   // [b,kvh,s,d] post-rope
__device__ float g_V[(size_t)B_SZ*NKVH*S_LEN*HD];   // [b,kvh,s,d]
__device__ float g_O[(size_t)B_SZ*S_LEN*D_MODEL];   // [b,s,h*d]

// ---------------- GEMM: C = A * W^T, A[M,K], W[N,K], both row-major -------------
// MODE 0: plain row-major C[M,N]
// MODE 1: rope + scatter to [b, h, s, d] (Hn heads)
// MODE 2: scatter to [b, h, s, d] (no rope)
#define BM 128
#define BN 128
#define BKG 8
#define TM 8
#define TN 8

template<int MODE>
__global__ __launch_bounds__(256)
void gemm_bt(const float* __restrict__ A, const float* __restrict__ W,
             float* __restrict__ C, int M, int N, int K,
             const float* __restrict__ fcos, const float* __restrict__ fsin,
             int Hn)
{
    __shared__ float As[BKG][BM];
    __shared__ float Ws[BKG][BN];
    const int tid = threadIdx.x;
    const int tx = tid & 15;
    const int ty = tid >> 4;
    const int m0 = blockIdx.y * BM;
    const int n0 = blockIdx.x * BN;
    const int lrow = tid >> 1;
    const int lcol = (tid & 1) * 4;
    const float* Ap = A + (size_t)(m0 + lrow) * K + lcol;
    const float* Wp = W + (size_t)(n0 + lrow) * K + lcol;

    float acc[TM][TN];
    #pragma unroll
    for (int i = 0; i < TM; i++)
        #pragma unroll
        for (int j = 0; j < TN; j++) acc[i][j] = 0.f;

    for (int k0 = 0; k0 < K; k0 += BKG) {
        float4 av = *(const float4*)(Ap + k0);
        float4 wv = *(const float4*)(Wp + k0);
        As[lcol+0][lrow] = av.x; As[lcol+1][lrow] = av.y;
        As[lcol+2][lrow] = av.z; As[lcol+3][lrow] = av.w;
        Ws[lcol+0][lrow] = wv.x; Ws[lcol+1][lrow] = wv.y;
        Ws[lcol+2][lrow] = wv.z; Ws[lcol+3][lrow] = wv.w;
        __syncthreads();
        #pragma unroll
        for (int kk = 0; kk < BKG; kk++) {
            float af[TM], wf[TN];
            *(float4*)(af)   = *(const float4*)&As[kk][ty*TM];
            *(float4*)(af+4) = *(const float4*)&As[kk][ty*TM+4];
            *(float4*)(wf)   = *(const float4*)&Ws[kk][tx*TN];
            *(float4*)(wf+4) = *(const float4*)&Ws[kk][tx*TN+4];
            #pragma unroll
            for (int i = 0; i < TM; i++)
                #pragma unroll
                for (int j = 0; j < TN; j++)
                    acc[i][j] += af[i]*wf[j];
        }
        __syncthreads();
    }

    if (MODE == 0) {
        #pragma unroll
        for (int i = 0; i < TM; i++) {
            int m = m0 + ty*TM + i;
            float* cp = C + (size_t)m*N + n0 + tx*TN;
            *(float4*)(cp)   = *(float4*)(&acc[i][0]);
            *(float4*)(cp+4) = *(float4*)(&acc[i][4]);
        }
    } else {
        #pragma unroll
        for (int i = 0; i < TM; i++) {
            int m = m0 + ty*TM + i;
            int b = m >> 11;             // /S_LEN
            int s = m & (S_LEN-1);
            #pragma unroll
            for (int j = 0; j < TN; j += 2) {
                int n = n0 + tx*TN + j;  // even
                int h = n >> 7;          // /HD
                int d = n & (HD-1);
                float* op = C + (((size_t)(b*Hn + h))*S_LEN + s)*HD + d;
                if (MODE == 1) {
                    int idx = d >> 1;
                    float c  = fcos[s*(HD/2) + idx];
                    float sn = fsin[s*(HD/2) + idx];
                    float xr = acc[i][j], xi = acc[i][j+1];
                    op[0] = xr*c - xi*sn;
                    op[1] = xr*sn + xi*c;
                } else {
                    op[0] = acc[i][j];
                    op[1] = acc[i][j+1];
                }
            }
        }
    }
}

// ---------------- Flash attention (fp32, causal, GQA) ----------------
#define BQ 64
#define BKT 32
#define QP 132
#define KP 132
#define PP 36
#define AT_SMEM ((BQ*QP + 2*BKT*KP + BQ*PP)*4)

__global__ __launch_bounds__(128)
void attn_kernel(const float* __restrict__ Qb, const float* __restrict__ Kb,
                 const float* __restrict__ Vb, float* __restrict__ Ob)
{
    extern __shared__ float sm[];
    float* Qs = sm;                  // [64][132]
    float* Ks = Qs + BQ*QP;          // [32][132]
    float* Vs = Ks + BKT*KP;         // [32][132]
    float* Ps = Vs + BKT*KP;         // [64][36]

    const int tid = threadIdx.x;
    const int rg  = tid >> 3;        // 16 row-groups, 4 rows each
    const int cg  = tid & 7;         // 8 col-groups
    const int bh  = blockIdx.y;
    const int b   = bh >> 4;
    const int h   = bh & 15;
    const int kvh = h >> 2;          // n_rep = 4
    const int qt  = blockIdx.x;
    const int q0  = qt * BQ;

    const float* Qg = Qb + ((size_t)(b*NH   + h  )*S_LEN + q0)*HD;
    const float* Kg = Kb + ((size_t)(b*NKVH + kvh)*S_LEN)*HD;
    const float* Vg = Vb + ((size_t)(b*NKVH + kvh)*S_LEN)*HD;

    for (int idx = tid*4; idx < BQ*HD; idx += 128*4) {
        int r = idx >> 7, d = idx & (HD-1);
        *(float4*)&Qs[r*QP + d] = *(const float4*)(Qg + r*HD + d);
    }

    float mrow[4], lrow[4], acc[4][16];
    #pragma unroll
    for (int i = 0; i < 4; i++) {
        mrow[i] = -1e30f; lrow[i] = 0.f;
        #pragma unroll
        for (int ii = 0; ii < 16; ii++) acc[i][ii] = 0.f;
    }

    const float scale = 0.08838834764831845f;  // 1/sqrt(128)
    const int nkt = (q0 + BQ) / BKT;
    __syncthreads();

    for (int kt = 0; kt < nkt; kt++) {
        const int k0 = kt * BKT;
        for (int idx = tid*4; idx < BKT*HD; idx += 128*4) {
            int r = idx >> 7, d = idx & (HD-1);
            *(float4*)&Ks[r*KP + d] = *(const float4*)(Kg + (size_t)(k0+r)*HD + d);
            *(float4*)&Vs[r*KP + d] = *(const float4*)(Vg + (size_t)(k0+r)*HD + d);
        }
        __syncthreads();

        // S = Q K^T : thread owns rows rg*4+{0..3}, cols cg+8*{0..3}
        float sc[4][4];
        #pragma unroll
        for (int i = 0; i < 4; i++)
            #pragma unroll
            for (int j = 0; j < 4; j++) sc[i][j] = 0.f;

        #pragma unroll 4
        for (int d = 0; d < HD; d += 4) {
            float4 qv[4], kv[4];
            #pragma unroll
            for (int i = 0; i < 4; i++) qv[i] = *(const float4*)&Qs[(rg*4+i)*QP + d];
            #pragma unroll
            for (int j = 0; j < 4; j++) kv[j] = *(const float4*)&Ks[(cg+8*j)*KP + d];
            #pragma unroll
            for (int i = 0; i < 4; i++)
                #pragma unroll
                for (int j = 0; j < 4; j++)
                    sc[i][j] += qv[i].x*kv[j].x + qv[i].y*kv[j].y
                              + qv[i].z*kv[j].z + qv[i].w*kv[j].w;
        }

        const bool needMask = (kt >= 2*qt);   // only the last two tiles cross diagonal
        #pragma unroll
        for (int i = 0; i < 4; i++) {
            const int qidx = q0 + rg*4 + i;
            float sv[4];
            #pragma unroll
            for (int j = 0; j < 4; j++) {
                float v = sc[i][j]*scale;
                if (needMask && (k0 + cg + 8*j) > qidx) v = -1e30f;
                sv[j] = v;
            }
            float tm = fmaxf(fmaxf(sv[0],sv[1]), fmaxf(sv[2],sv[3]));
            tm = fmaxf(tm, __shfl_xor_sync(0xffffffffu, tm, 1));
            tm = fmaxf(tm, __shfl_xor_sync(0xffffffffu, tm, 2));
            tm = fmaxf(tm, __shfl_xor_sync(0xffffffffu, tm, 4));
            float newm = fmaxf(mrow[i], tm);
            float corr;
            float psum = 0.f;
            float* prow = &Ps[(rg*4+i)*PP];
            if (newm < -8e29f) {
                // row entirely masked so far: contribute nothing
                corr = 1.f;
                #pragma unroll
                for (int j = 0; j < 4; j++) prow[cg + 8*j] = 0.f;
            } else {
                corr = expf(mrow[i] - newm);
                #pragma unroll
                for (int j = 0; j < 4; j++) {
                    float p = expf(sv[j] - newm);   // masked: exp(-huge) -> 0
                    prow[cg + 8*j] = p;
                    psum += p;
                }
            }
            psum += __shfl_xor_sync(0xffffffffu, psum, 1);
            psum += __shfl_xor_sync(0xffffffffu, psum, 2);
            psum += __shfl_xor_sync(0xffffffffu, psum, 4);
            mrow[i] = newm;
            lrow[i] = lrow[i]*corr + psum;
            #pragma unroll
            for (int ii = 0; ii < 16; ii++) acc[i][ii] *= corr;
        }
        __syncthreads();

        // acc += P V : thread owns rows rg*4+{0..3}, cols cg+8*{0..15}
        #pragma unroll 4
        for (int k = 0; k < BKT; k++) {
            float pv[4];
            #pragma unroll
            for (int i = 0; i < 4; i++) pv[i] = Ps[(rg*4+i)*PP + k];
            #pragma unroll
            for (int ii = 0; ii < 16; ii++) {
                float v = Vs[k*KP + cg + 8*ii];
                #pragma unroll
                for (int i = 0; i < 4; i++) acc[i][ii] += pv[i]*v;
            }
        }
        __syncthreads();
    }

    #pragma unroll
    for (int i = 0; i < 4; i++) {
        float inv = 1.f / lrow[i];
        int srow = q0 + rg*4 + i;
        float* op = Ob + ((size_t)b*S_LEN + srow)*D_MODEL + h*HD;
        #pragma unroll
        for (int ii = 0; ii < 16; ii++)
            op[cg + 8*ii] = acc[i][ii]*inv;
    }
}

extern "C" void kernel_launch(void* const* d_in, const int* in_sizes, int n_in,
                              void* d_out, int out_size)
{
    const float* x    = (const float*)d_in[0];
    const float* fcos = (const float*)d_in[1];
    const float* fsin = (const float*)d_in[2];
    const float* wq   = (const float*)d_in[3];
    const float* wk   = (const float*)d_in[4];
    const float* wv   = (const float*)d_in[5];
    const float* wo   = (const float*)d_in[6];
    float* out = (float*)d_out;

    float *pQ, *pK, *pV, *pO;
    cudaGetSymbolAddress((void**)&pQ, g_Q);
    cudaGetSymbolAddress((void**)&pK, g_K);
    cudaGetSymbolAddress((void**)&pV, g_V);
    cudaGetSymbolAddress((void**)&pO, g_O);

    cudaFuncSetAttribute(attn_kernel,
                         cudaFuncAttributeMaxDynamicSharedMemorySize, AT_SMEM);

    dim3 thr(256);
    // Q projection + rope -> g_Q [b,h,s,d]
    gemm_bt<1><<<dim3(D_MODEL/BN, MROWS/BM), thr>>>(x, wq, pQ, MROWS, D_MODEL, D_MODEL, fcos, fsin, NH);
    // K projection + rope -> g_K [b,kvh,s,d]
    gemm_bt<1><<<dim3((NKVH*HD)/BN, MROWS/BM), thr>>>(x, wk, pK, MROWS, NKVH*HD, D_MODEL, fcos, fsin, NKVH);
    // V projection -> g_V [b,kvh,s,d]
    gemm_bt<2><<<dim3((NKVH*HD)/BN, MROWS/BM), thr>>>(x, wv, pV, MROWS, NKVH*HD, D_MODEL, nullptr, nullptr, NKVH);
    // attention -> g_O [b,s,h*d]
    attn_kernel<<<dim3(S_LEN/BQ, B_SZ*NH), 128, AT_SMEM>>>(pQ, pK, pV, pO);
    // output projection -> d_out
    gemm_bt<0><<<dim3(D_MODEL/BN, MROWS/BM), thr>>>(pO, wo, out, MROWS, D_MODEL, D_MODEL, nullptr, nullptr, 0);
}

// round 3
// speedup vs baseline: 1.7189x; 1.7189x over previous
#include <cuda_runtime.h>
#include <cuda_bf16.h>
#include <cstdint>
#include <math.h>

#define B_SZ 2
#define S_LEN 2048
#define D_MODEL 2048
#define NH 16
#define NKVH 4
#define HD 128
#define MROWS (B_SZ*S_LEN)

// Scratch (allocation-free rule: __device__ globals)
__device__ float g_Q[(size_t)B_SZ*NH*S_LEN*HD];     // [b,h,s,d] post-rope
__device__ float g_K[(size_t)B_SZ*NKVH*S_LEN*HD];   // [b,kvh,s,d] post-rope
__device__ float g_V[(size_t)B_SZ*NKVH*S_LEN*HD];   // [b,kvh,s,d]
__device__ float g_O[(size_t)B_SZ*S_LEN*D_MODEL];   // [b,s,h*d]

__device__ __forceinline__ uint32_t f2tf32(float f){
    uint32_t u; asm("cvt.rna.tf32.f32 %0, %1;" : "=r"(u) : "f"(f)); return u;
}
__device__ __forceinline__ void mma_tf32(float* c, const uint4& a, const uint2& b){
    asm volatile("mma.sync.aligned.m16n8k8.row.col.f32.tf32.tf32.f32 "
        "{%0,%1,%2,%3}, {%4,%5,%6,%7}, {%8,%9}, {%0,%1,%2,%3};"
        : "+f"(c[0]), "+f"(c[1]), "+f"(c[2]), "+f"(c[3])
        : "r"(a.x), "r"(a.y), "r"(a.z), "r"(a.w), "r"(b.x), "r"(b.y));
}

// ==================== HMMA tf32 GEMM: C = A * W^T ====================
// A[M,2048] row-major, W[N,2048] row-major. Tile 128x128, BK=32, 256 thr.
// Smem in fragment-major layout:
//   A: [2][mt=8][kt=4][128]  (thread's 4 A-frag regs contiguous -> LDS.128)
//   B: [2][nt=16][kt=4][64]  (thread's 2 B-frag regs contiguous -> LDS.64)
// MODE 0: plain row-major C[M,N]
// MODE 1: rope + scatter to [b,h,s,d]
// MODE 2: scatter to [b,h,s,d]
#define G_NCH 64
#define G_SMEM 65536

template<int MODE>
__global__ __launch_bounds__(256)
void gemm_tc(const float* __restrict__ A, const float* __restrict__ W,
             float* __restrict__ C, int N,
             const float* __restrict__ fcos, const float* __restrict__ fsin, int Hn)
{
    extern __shared__ uint32_t smu[];
    uint32_t* Asu = smu;           // 2 * 4096
    uint32_t* Bsu = smu + 8192;    // 2 * 4096

    const int tid  = threadIdx.x;
    const int wid  = tid >> 5;
    const int lane = tid & 31;
    const int wm   = wid & 3;      // warp m index (0..3) -> rows wm*32
    const int wn   = wid >> 2;     // warp n index (0..1) -> cols wn*64
    const int m0 = blockIdx.y * 128;
    const int n0 = blockIdx.x * 128;

    // global-load mapping: thread loads rows r0+32i (i=0..3), cols fc*4..fc*4+3
    const int fc = tid & 7;
    const int r0 = tid >> 3;

    // fragment-store constants
    const int row16 = r0 & 15;
    const int mtb   = r0 >> 4;          // 0/1
    const int ktc   = fc >> 1;          // 0..3
    const int rA    = ((row16 >> 3) & 1) + ((fc & 1) << 1);
    const int laneApart = (row16 & 7) * 16 + rA;     // + 4*j
    const int n8  = r0 & 7;
    const int ntb = r0 >> 3;            // 0..3
    const int rB  = fc & 1;
    const int laneBpart = n8 * 8 + rB;               // + 2*j

    const float* Ap = A + (size_t)(m0 + r0)*D_MODEL + fc*4;
    const float* Wp = W + (size_t)(n0 + r0)*D_MODEL + fc*4;

    float4 ra[4], rw[4];
    auto PREF = [&](int kc){
        const float* a = Ap + kc*32;
        const float* w = Wp + kc*32;
        #pragma unroll
        for (int i=0;i<4;i++){
            ra[i] = *(const float4*)(a + (size_t)i*32*D_MODEL);
            rw[i] = *(const float4*)(w + (size_t)i*32*D_MODEL);
        }
    };
    auto STS = [&](int b){
        uint32_t* Ab = Asu + b*4096;
        uint32_t* Bb = Bsu + b*4096;
        #pragma unroll
        for (int i=0;i<4;i++){
            int baseA = ((mtb + 2*i)*4 + ktc)*128 + laneApart;
            Ab[baseA + 0 ] = f2tf32(ra[i].x);
            Ab[baseA + 4 ] = f2tf32(ra[i].y);
            Ab[baseA + 8 ] = f2tf32(ra[i].z);
            Ab[baseA + 12] = f2tf32(ra[i].w);
            int baseB = ((ntb + 4*i)*4 + ktc)*64 + laneBpart;
            Bb[baseB + 0] = f2tf32(rw[i].x);
            Bb[baseB + 2] = f2tf32(rw[i].y);
            Bb[baseB + 4] = f2tf32(rw[i].z);
            Bb[baseB + 6] = f2tf32(rw[i].w);
        }
    };

    float acc[2][8][4];
    #pragma unroll
    for (int mi=0;mi<2;mi++)
        #pragma unroll
        for (int n=0;n<8;n++)
            #pragma unroll
            for (int r=0;r<4;r++) acc[mi][n][r] = 0.f;

    auto MMAS = [&](int b){
        const uint32_t* Ab = Asu + b*4096 + wm*2*512;
        const uint32_t* Bb = Bsu + b*4096 + wn*8*256;
        #pragma unroll
        for (int kt=0;kt<4;kt++){
            uint4 af[2];
            af[0] = *(const uint4*)(Ab + (0*4 + kt)*128 + lane*4);
            af[1] = *(const uint4*)(Ab + (1*4 + kt)*128 + lane*4);
            uint2 bf[8];
            #pragma unroll
            for (int n=0;n<8;n++)
                bf[n] = *(const uint2*)(Bb + (n*4 + kt)*64 + lane*2);
            #pragma unroll
            for (int mi=0;mi<2;mi++)
                #pragma unroll
                for (int n=0;n<8;n++)
                    mma_tf32(acc[mi][n], af[mi], bf[n]);
        }
    };

    PREF(0); STS(0);
    __syncthreads();
    PREF(1);

    for (int i = 0; i < G_NCH; i++) {
        const int cur = i & 1;
        if (i + 1 < G_NCH) STS(1 - cur);
        if (i + 2 < G_NCH) PREF(i + 2);
        MMAS(cur);
        __syncthreads();
    }

    // -------- epilogue --------
    const int l4 = lane >> 2;
    const int l2 = (lane & 3) * 2;
    #pragma unroll
    for (int mi = 0; mi < 2; mi++) {
        #pragma unroll
        for (int n = 0; n < 8; n++) {
            const int col = n0 + wn*64 + n*8 + l2;
            #pragma unroll
            for (int half = 0; half < 2; half++) {
                const int row = m0 + wm*32 + mi*16 + l4 + half*8;
                float xr = acc[mi][n][half*2 + 0];
                float xi = acc[mi][n][half*2 + 1];
                if (MODE == 0) {
                    float2 o; o.x = xr; o.y = xi;
                    *(float2*)(C + (size_t)row*N + col) = o;
                } else {
                    const int b = row >> 11;
                    const int s = row & (S_LEN-1);
                    const int h = col >> 7;
                    const int d = col & (HD-1);
                    float* op = C + (((size_t)(b*Hn + h))*S_LEN + s)*HD + d;
                    if (MODE == 1) {
                        float cs = fcos[s*(HD/2) + (d>>1)];
                        float sn = fsin[s*(HD/2) + (d>>1)];
                        float2 o; o.x = xr*cs - xi*sn; o.y = xr*sn + xi*cs;
                        *(float2*)op = o;
                    } else {
                        float2 o; o.x = xr; o.y = xi;
                        *(float2*)op = o;
                    }
                }
            }
        }
    }
}

// ---------------- Flash attention (fp32, causal, GQA) ----------------
#define BQ 64
#define BKT 32
#define QP 132
#define KP 132
#define PP 36
#define AT_SMEM ((BQ*QP + 2*BKT*KP + BQ*PP)*4)

__global__ __launch_bounds__(128)
void attn_kernel(const float* __restrict__ Qb, const float* __restrict__ Kb,
                 const float* __restrict__ Vb, float* __restrict__ Ob)
{
    extern __shared__ float smf[];
    float* Qs = smf;                 // [64][132]
    float* Ks = Qs + BQ*QP;          // [32][132]
    float* Vs = Ks + BKT*KP;         // [32][132]
    float* Ps = Vs + BKT*KP;         // [64][36]

    const int tid = threadIdx.x;
    const int rg  = tid >> 3;        // 16 row-groups, 4 rows each
    const int cg  = tid & 7;         // 8 col-groups
    const int bh  = blockIdx.y;
    const int b   = bh >> 4;
    const int h   = bh & 15;
    const int kvh = h >> 2;          // n_rep = 4
    const int qt  = blockIdx.x;
    const int q0  = qt * BQ;

    const float* Qg = Qb + ((size_t)(b*NH   + h  )*S_LEN + q0)*HD;
    const float* Kg = Kb + ((size_t)(b*NKVH + kvh)*S_LEN)*HD;
    const float* Vg = Vb + ((size_t)(b*NKVH + kvh)*S_LEN)*HD;

    for (int idx = tid*4; idx < BQ*HD; idx += 128*4) {
        int r = idx >> 7, d = idx & (HD-1);
        *(float4*)&Qs[r*QP + d] = *(const float4*)(Qg + r*HD + d);
    }

    float mrow[4], lrow[4];
    float4 acc[4][4];
    #pragma unroll
    for (int i = 0; i < 4; i++) {
        mrow[i] = -1e30f; lrow[i] = 0.f;
        #pragma unroll
        for (int g = 0; g < 4; g++) acc[i][g] = make_float4(0.f,0.f,0.f,0.f);
    }

    const float scale = 0.08838834764831845f;  // 1/sqrt(128)
    const int nkt = (q0 + BQ) / BKT;
    __syncthreads();

    for (int kt = 0; kt < nkt; kt++) {
        const int k0 = kt * BKT;
        for (int idx = tid*4; idx < BKT*HD; idx += 128*4) {
            int r = idx >> 7, d = idx & (HD-1);
            *(float4*)&Ks[r*KP + d] = *(const float4*)(Kg + (size_t)(k0+r)*HD + d);
            *(float4*)&Vs[r*KP + d] = *(const float4*)(Vg + (size_t)(k0+r)*HD + d);
        }
        __syncthreads();

        float sc[4][4];
        #pragma unroll
        for (int i = 0; i < 4; i++)
            #pragma unroll
            for (int j = 0; j < 4; j++) sc[i][j] = 0.f;

        #pragma unroll 4
        for (int d = 0; d < HD; d += 4) {
            float4 qv[4], kv[4];
            #pragma unroll
            for (int i = 0; i < 4; i++) qv[i] = *(const float4*)&Qs[(rg*4+i)*QP + d];
            #pragma unroll
            for (int j = 0; j < 4; j++) kv[j] = *(const float4*)&Ks[(cg+8*j)*KP + d];
            #pragma unroll
            for (int i = 0; i < 4; i++)
                #pragma unroll
                for (int j = 0; j < 4; j++)
                    sc[i][j] += qv[i].x*kv[j].x + qv[i].y*kv[j].y
                              + qv[i].z*kv[j].z + qv[i].w*kv[j].w;
        }

        const bool needMask = (kt >= 2*qt);
        #pragma unroll
        for (int i = 0; i < 4; i++) {
            const int qidx = q0 + rg*4 + i;
            float sv[4];
            #pragma unroll
            for (int j = 0; j < 4; j++) {
                float v = sc[i][j]*scale;
                if (needMask && (k0 + cg + 8*j) > qidx) v = -1e30f;
                sv[j] = v;
            }
            float tm = fmaxf(fmaxf(sv[0],sv[1]), fmaxf(sv[2],sv[3]));
            tm = fmaxf(tm, __shfl_xor_sync(0xffffffffu, tm, 1));
            tm = fmaxf(tm, __shfl_xor_sync(0xffffffffu, tm, 2));
            tm = fmaxf(tm, __shfl_xor_sync(0xffffffffu, tm, 4));
            float newm = fmaxf(mrow[i], tm);
            float corr;
            float psum = 0.f;
            float* prow = &Ps[(rg*4+i)*PP];
            if (newm < -8e29f) {
                corr = 1.f;
                #pragma unroll
                for (int j = 0; j < 4; j++) prow[cg + 8*j] = 0.f;
            } else {
                corr = __expf(mrow[i] - newm);
                #pragma unroll
                for (int j = 0; j < 4; j++) {
                    float p = __expf(sv[j] - newm);
                    prow[cg + 8*j] = p;
                    psum += p;
                }
            }
            psum += __shfl_xor_sync(0xffffffffu, psum, 1);
            psum += __shfl_xor_sync(0xffffffffu, psum, 2);
            psum += __shfl_xor_sync(0xffffffffu, psum, 4);
            mrow[i] = newm;
            lrow[i] = lrow[i]*corr + psum;
            #pragma unroll
            for (int g = 0; g < 4; g++) {
                acc[i][g].x *= corr; acc[i][g].y *= corr;
                acc[i][g].z *= corr; acc[i][g].w *= corr;
            }
        }
        __syncthreads();

        #pragma unroll 4
        for (int k = 0; k < BKT; k++) {
            float pv[4];
            #pragma unroll
            for (int i = 0; i < 4; i++) pv[i] = Ps[(rg*4+i)*PP + k];
            #pragma unroll
            for (int g = 0; g < 4; g++) {
                float4 v = *(const float4*)&Vs[k*KP + cg*4 + 32*g];
                #pragma unroll
                for (int i = 0; i < 4; i++) {
                    acc[i][g].x += pv[i]*v.x;
                    acc[i][g].y += pv[i]*v.y;
                    acc[i][g].z += pv[i]*v.z;
                    acc[i][g].w += pv[i]*v.w;
                }
            }
        }
        __syncthreads();
    }

    #pragma unroll
    for (int i = 0; i < 4; i++) {
        float inv = 1.f / lrow[i];
        int srow = q0 + rg*4 + i;
        float* op = Ob + ((size_t)b*S_LEN + srow)*D_MODEL + h*HD;
        #pragma unroll
        for (int g = 0; g < 4; g++) {
            float4 o;
            o.x = acc[i][g].x*inv; o.y = acc[i][g].y*inv;
            o.z = acc[i][g].z*inv; o.w = acc[i][g].w*inv;
            *(float4*)(op + cg*4 + 32*g) = o;
        }
    }
}

extern "C" void kernel_launch(void* const* d_in, const int* in_sizes, int n_in,
                              void* d_out, int out_size)
{
    const float* x    = (const float*)d_in[0];
    const float* fcos = (const float*)d_in[1];
    const float* fsin = (const float*)d_in[2];
    const float* wq   = (const float*)d_in[3];
    const float* wk   = (const float*)d_in[4];
    const float* wv   = (const float*)d_in[5];
    const float* wo   = (const float*)d_in[6];
    float* out = (float*)d_out;

    float *pQ, *pK, *pV, *pO;
    cudaGetSymbolAddress((void**)&pQ, g_Q);
    cudaGetSymbolAddress((void**)&pK, g_K);
    cudaGetSymbolAddress((void**)&pV, g_V);
    cudaGetSymbolAddress((void**)&pO, g_O);

    cudaFuncSetAttribute(gemm_tc<0>, cudaFuncAttributeMaxDynamicSharedMemorySize, G_SMEM);
    cudaFuncSetAttribute(gemm_tc<1>, cudaFuncAttributeMaxDynamicSharedMemorySize, G_SMEM);
    cudaFuncSetAttribute(gemm_tc<2>, cudaFuncAttributeMaxDynamicSharedMemorySize, G_SMEM);
    cudaFuncSetAttribute(attn_kernel, cudaFuncAttributeMaxDynamicSharedMemorySize, AT_SMEM);

    gemm_tc<1><<<dim3(D_MODEL/128, MROWS/128), 256, G_SMEM>>>(x, wq, pQ, D_MODEL, fcos, fsin, NH);
    gemm_tc<1><<<dim3((NKVH*HD)/128, MROWS/128), 256, G_SMEM>>>(x, wk, pK, NKVH*HD, fcos, fsin, NKVH);
    gemm_tc<2><<<dim3((NKVH*HD)/128, MROWS/128), 256, G_SMEM>>>(x, wv, pV, NKVH*HD, nullptr, nullptr, NKVH);
    attn_kernel<<<dim3(S_LEN/BQ, B_SZ*NH), 128, AT_SMEM>>>(pQ, pK, pV, pO);
    gemm_tc<0><<<dim3(D_MODEL/128, MROWS/128), 256, G_SMEM>>>(pO, wo, out, D_MODEL, nullptr, nullptr, 0);
}

// round 6
// speedup vs baseline: 4.4805x; 2.6066x over previous
#include <cuda_runtime.h>
#include <cuda_fp16.h>
#include <cstdint>
#include <math.h>

#define B_SZ 2
#define S_LEN 2048
#define D_MODEL 2048
#define NH 16
#define NKVH 4
#define HD 128
#define MROWS (B_SZ*S_LEN)

// Scratch (allocation-free rule: __device__ globals)
__device__ float g_Q[(size_t)B_SZ*NH*S_LEN*HD];     // [b,h,s,d] post-rope
__device__ float g_K[(size_t)B_SZ*NKVH*S_LEN*HD];   // [b,kvh,s,d] post-rope
__device__ float g_V[(size_t)B_SZ*NKVH*S_LEN*HD];   // [b,kvh,s,d]
__device__ float g_O[(size_t)B_SZ*S_LEN*D_MODEL];   // [b,s,h*d]

__device__ __forceinline__ uint32_t pk(float a, float b){
    __half2 h = __floats2half2_rn(a, b);
    return *reinterpret_cast<uint32_t*>(&h);
}
__device__ __forceinline__ void mma_f16(float* c, const uint4& a, const uint2& b){
    asm volatile("mma.sync.aligned.m16n8k16.row.col.f32.f16.f16.f32 "
        "{%0,%1,%2,%3}, {%4,%5,%6,%7}, {%8,%9}, {%0,%1,%2,%3};"
        : "+f"(c[0]), "+f"(c[1]), "+f"(c[2]), "+f"(c[3])
        : "r"(a.x), "r"(a.y), "r"(a.z), "r"(a.w), "r"(b.x), "r"(b.y));
}

// ==================== HMMA fp16 GEMM: C = A * W^T ====================
// Tile 128x128, BK=32, 256 thr, double-buffered fragment-major smem (fp16).
//   A buf: [mt=8][kt=2][128] u32   B buf: [nt=16][kt=2][64] u32   (8KB each)
// MODE 0: plain row-major C[M,N].  MODE 3: fused QKV (runtime block routing).
#define G_NCH 64
#define G_SMEM 32768

template<int MODE>
__global__ __launch_bounds__(256)
void gemm_f16(const float* __restrict__ A,
              const float* __restrict__ Wq, const float* __restrict__ Wk,
              const float* __restrict__ Wv,
              float* __restrict__ Cq, float* __restrict__ Ck, float* __restrict__ Cv,
              const float* __restrict__ fcos, const float* __restrict__ fsin)
{
    extern __shared__ uint32_t smu[];
    uint32_t* Asu = smu;           // 2 * 2048
    uint32_t* Bsu = smu + 4096;    // 2 * 2048

    const int tid  = threadIdx.x;
    const int wid  = tid >> 5;
    const int lane = tid & 31;
    const int wm   = wid & 3;
    const int wn   = wid >> 2;
    const int m0 = blockIdx.y * 128;
    const int n0g = blockIdx.x * 128;

    const float* W; float* C; int n0; int Hn = 0; int rope = 0;
    if (MODE == 0) {
        W = Wq; C = Cq; n0 = n0g;
    } else {
        if (n0g < 2048)      { W = Wq; C = Cq; n0 = n0g;        Hn = NH;   rope = 1; }
        else if (n0g < 2560) { W = Wk; C = Ck; n0 = n0g - 2048; Hn = NKVH; rope = 1; }
        else                 { W = Wv; C = Cv; n0 = n0g - 2560; Hn = NKVH; rope = 0; }
    }

    const int fc = tid & 7;      // float4 col within 32-wide chunk
    const int r0 = tid >> 3;     // 0..31 base row

    const float* Ap = A + (size_t)(m0 + r0)*D_MODEL + fc*4;
    const float* Wp = W + (size_t)(n0 + r0)*D_MODEL + fc*4;

    // fragment-store constants
    const int ktc = fc >> 2;            // 0/1
    const int kp  = (fc*2) & 7;         // even kp
    const int wA  = (kp & 3)*4 + 2*(kp >> 2);
    const int wB  = (kp & 3)*2 + (kp >> 2);

    float4 ra[4], rw[4];
    auto PREF = [&](int kc){
        const float* a = Ap + kc*32;
        const float* w = Wp + kc*32;
        #pragma unroll
        for (int i=0;i<4;i++){
            ra[i] = *(const float4*)(a + (size_t)i*32*D_MODEL);
            rw[i] = *(const float4*)(w + (size_t)i*32*D_MODEL);
        }
    };
    auto STS = [&](int b){
        uint32_t* Ab = Asu + b*2048;
        uint32_t* Bb = Bsu + b*2048;
        #pragma unroll
        for (int i=0;i<4;i++){
            const int row = r0 + 32*i;
            const int mt = row >> 4, row16 = row & 15;
            int baseA = ((mt*2 + ktc)*128) + (row16 & 7)*16 + (row16 >> 3) + wA;
            Ab[baseA]     = pk(ra[i].x, ra[i].y);
            Ab[baseA + 4] = pk(ra[i].z, ra[i].w);
            const int nt = row >> 3, n8 = row & 7;
            int baseB = ((nt*2 + ktc)*64) + n8*8 + wB;
            Bb[baseB]     = pk(rw[i].x, rw[i].y);
            Bb[baseB + 2] = pk(rw[i].z, rw[i].w);
        }
    };

    float acc[2][8][4];
    #pragma unroll
    for (int mi=0;mi<2;mi++)
        #pragma unroll
        for (int n=0;n<8;n++)
            #pragma unroll
            for (int r=0;r<4;r++) acc[mi][n][r] = 0.f;

    auto MMAS = [&](int b){
        const uint32_t* Ab = Asu + b*2048;
        const uint32_t* Bb = Bsu + b*2048;
        #pragma unroll
        for (int kt=0;kt<2;kt++){
            uint4 af[2];
            #pragma unroll
            for (int mi=0;mi<2;mi++)
                af[mi] = *(const uint4*)(Ab + ((2*wm+mi)*2 + kt)*128 + lane*4);
            uint2 bf[8];
            #pragma unroll
            for (int n=0;n<8;n++)
                bf[n] = *(const uint2*)(Bb + ((wn*8+n)*2 + kt)*64 + lane*2);
            #pragma unroll
            for (int mi=0;mi<2;mi++)
                #pragma unroll
                for (int n=0;n<8;n++)
                    mma_f16(acc[mi][n], af[mi], bf[n]);
        }
    };

    PREF(0); STS(0);
    __syncthreads();
    PREF(1);

    for (int i = 0; i < G_NCH; i++) {
        const int cur = i & 1;
        if (i + 1 < G_NCH) STS(1 - cur);
        if (i + 2 < G_NCH) PREF(i + 2);
        MMAS(cur);
        __syncthreads();
    }

    // -------- epilogue (C frag: rows l4/l4+8, cols 2*(lane&3)+{0,1}) --------
    const int l4 = lane >> 2;
    const int l2 = (lane & 3) * 2;
    #pragma unroll
    for (int mi = 0; mi < 2; mi++) {
        #pragma unroll
        for (int n = 0; n < 8; n++) {
            const int col = n0 + wn*64 + n*8 + l2;
            #pragma unroll
            for (int half = 0; half < 2; half++) {
                const int row = m0 + wm*32 + mi*16 + l4 + half*8;
                float xr = acc[mi][n][half*2 + 0];
                float xi = acc[mi][n][half*2 + 1];
                if (MODE == 0) {
                    float2 o; o.x = xr; o.y = xi;
                    *(float2*)(C + (size_t)row*D_MODEL + col) = o;
                } else {
                    const int b = row >> 11;
                    const int s = row & (S_LEN-1);
                    const int h = col >> 7;
                    const int d = col & (HD-1);
                    float* op = C + (((size_t)(b*Hn + h))*S_LEN + s)*HD + d;
                    float2 o;
                    if (rope) {
                        float cs = fcos[s*(HD/2) + (d>>1)];
                        float sn = fsin[s*(HD/2) + (d>>1)];
                        o.x = xr*cs - xi*sn; o.y = xr*sn + xi*cs;
                    } else {
                        o.x = xr; o.y = xi;
                    }
                    *(float2*)op = o;
                }
            }
        }
    }
}

// ========== Tensor-core flash attention (fp16 mma, causal, GQA) ==========
// BQ=64, BKT=64, 128 threads (4 warps, warp w owns 16 q-rows).
// Smem (u32 words): Qs [mt4][kt8][128]=4096, Ks [nt8][kt8][64]=4096,
//                   Vs [nt16][kt4][64]=4096, Ps [mt4][kt4][128]=2048
#define AQ_OFF 0
#define AK_OFF 4096
#define AV_OFF 8192
#define AP_OFF 12288
#define AT_SMEM (14336*4)

__global__ __launch_bounds__(128)
void attn_tc(const float* __restrict__ Qb, const float* __restrict__ Kb,
             const float* __restrict__ Vb, float* __restrict__ Ob)
{
    extern __shared__ uint32_t s[];
    uint32_t* Qs = s + AQ_OFF;
    uint32_t* Ks = s + AK_OFF;
    uint32_t* Vs = s + AV_OFF;
    uint32_t* Ps = s + AP_OFF;

    const int tid  = threadIdx.x;
    const int wid  = tid >> 5;
    const int lane = tid & 31;
    const int b   = blockIdx.y >> 4;
    const int h   = blockIdx.y & 15;
    const int kvh = h >> 2;
    const int qt  = blockIdx.x;
    const int q0  = qt * 64;

    const float* Qg = Qb + ((size_t)(b*NH   + h  )*S_LEN + q0)*HD;
    const float* Kg = Kb + ((size_t)(b*NKVH + kvh)*S_LEN)*HD;
    const float* Vg = Vb + ((size_t)(b*NKVH + kvh)*S_LEN)*HD;

    // ---- load Q once (A-frag-major, fp16) ----
    #pragma unroll
    for (int it = 0; it < 16; it++) {
        int idx = tid + 128*it;
        int row = idx >> 5, c4 = idx & 31, d0 = c4*4;
        float4 f = *(const float4*)(Qg + (size_t)row*HD + d0);
        int mt = row >> 4, row16 = row & 15;
        int kt = d0 >> 4, kpq = (d0 >> 1) & 7;
        int base = (mt*8 + kt)*128 + (row16 & 7)*16 + (kpq & 3)*4 + (row16 >> 3) + 2*(kpq >> 2);
        Qs[base]     = pk(f.x, f.y);
        Qs[base + 4] = pk(f.z, f.w);
    }

    float m0 = -1e30f, m1 = -1e30f, l0 = 0.f, l1 = 0.f;
    float o[16][4];
    #pragma unroll
    for (int nt=0;nt<16;nt++)
        #pragma unroll
        for (int r=0;r<4;r++) o[nt][r] = 0.f;

    const float scale = 0.08838834764831845f;  // 1/sqrt(128)
    const int qlo = q0 + wid*16 + (lane >> 2);
    const int qhi = qlo + 8;
    const int nkt = qt + 1;

    for (int tile = 0; tile < nkt; tile++) {
        const int k0 = tile * 64;
        __syncthreads();
        // ---- load K tile (B-frag for S): 64 rows x 32 float4 = 2048 ----
        #pragma unroll
        for (int it = 0; it < 16; it++) {
            int idx = tid + 128*it;
            int r = idx >> 5, c4 = idx & 31, d0 = c4*4;
            float4 f = *(const float4*)(Kg + (size_t)(k0 + r)*HD + d0);
            int nt = r >> 3, n8 = r & 7;
            int kt = d0 >> 4, kpq = (d0 >> 1) & 7;
            int base = (nt*8 + kt)*64 + n8*8 + (kpq & 3)*2 + (kpq >> 2);
            Ks[base]     = pk(f.x, f.y);
            Ks[base + 2] = pk(f.z, f.w);
        }
        // ---- load V tile (B-frag for PV: pairs of keys packed) ----
        #pragma unroll
        for (int it = 0; it < 8; it++) {
            int u = tid + 128*it;
            int kp2 = u >> 5, c4 = u & 31, d0 = c4*4;
            int key = kp2*2;
            float4 fa = *(const float4*)(Vg + (size_t)(k0 + key    )*HD + d0);
            float4 fb = *(const float4*)(Vg + (size_t)(k0 + key + 1)*HD + d0);
            int kt = key >> 4, kpq = kp2 & 7;
            int ntb = d0 >> 3, n8b = d0 & 7;
            int base = (ntb*4 + kt)*64 + (kpq & 3)*2 + (kpq >> 2) + n8b*8;
            Vs[base + 0 ] = pk(fa.x, fb.x);
            Vs[base + 8 ] = pk(fa.y, fb.y);
            Vs[base + 16] = pk(fa.z, fb.z);
            Vs[base + 24] = pk(fa.w, fb.w);
        }
        __syncthreads();

        // ---- S = Q K^T (16 x 64 per warp) ----
        float sacc[8][4];
        #pragma unroll
        for (int n=0;n<8;n++)
            #pragma unroll
            for (int r=0;r<4;r++) sacc[n][r] = 0.f;
        #pragma unroll
        for (int kt = 0; kt < 8; kt++) {
            uint4 af = *(const uint4*)(Qs + (wid*8 + kt)*128 + lane*4);
            #pragma unroll
            for (int n = 0; n < 8; n++) {
                uint2 bf = *(const uint2*)(Ks + (n*8 + kt)*64 + lane*2);
                mma_f16(sacc[n], af, bf);
            }
        }

        // ---- online softmax ----
        const bool diag = (tile == nkt - 1);
        float mx0 = -1e30f, mx1 = -1e30f;
        #pragma unroll
        for (int n = 0; n < 8; n++) {
            float v0 = sacc[n][0]*scale, v1 = sacc[n][1]*scale;
            float v2 = sacc[n][2]*scale, v3 = sacc[n][3]*scale;
            if (diag) {
                int c0 = k0 + n*8 + (lane & 3)*2;
                if (c0     > qlo) v0 = -1e30f;
                if (c0 + 1 > qlo) v1 = -1e30f;
                if (c0     > qhi) v2 = -1e30f;
                if (c0 + 1 > qhi) v3 = -1e30f;
            }
            sacc[n][0]=v0; sacc[n][1]=v1; sacc[n][2]=v2; sacc[n][3]=v3;
            mx0 = fmaxf(mx0, fmaxf(v0, v1));
            mx1 = fmaxf(mx1, fmaxf(v2, v3));
        }
        mx0 = fmaxf(mx0, __shfl_xor_sync(0xffffffffu, mx0, 1));
        mx0 = fmaxf(mx0, __shfl_xor_sync(0xffffffffu, mx0, 2));
        mx1 = fmaxf(mx1, __shfl_xor_sync(0xffffffffu, mx1, 1));
        mx1 = fmaxf(mx1, __shfl_xor_sync(0xffffffffu, mx1, 2));
        float nm0 = fmaxf(m0, mx0), nm1 = fmaxf(m1, mx1);
        float cr0 = __expf(m0 - nm0), cr1 = __expf(m1 - nm1);
        m0 = nm0; m1 = nm1;

        float s0 = 0.f, s1 = 0.f;
        #pragma unroll
        for (int n = 0; n < 8; n++) {
            float p0 = __expf(sacc[n][0] - nm0);
            float p1 = __expf(sacc[n][1] - nm0);
            float p2 = __expf(sacc[n][2] - nm1);
            float p3 = __expf(sacc[n][3] - nm1);
            s0 += p0 + p1; s1 += p2 + p3;
            uint2 w; w.x = pk(p0, p1); w.y = pk(p2, p3);
            *(uint2*)(Ps + (wid*4 + (n>>1))*128 + (lane>>2)*16 + (lane&3)*4 + 2*(n&1)) = w;
        }
        s0 += __shfl_xor_sync(0xffffffffu, s0, 1);
        s0 += __shfl_xor_sync(0xffffffffu, s0, 2);
        s1 += __shfl_xor_sync(0xffffffffu, s1, 1);
        s1 += __shfl_xor_sync(0xffffffffu, s1, 2);
        l0 = l0*cr0 + s0;
        l1 = l1*cr1 + s1;
        #pragma unroll
        for (int nt = 0; nt < 16; nt++) {
            o[nt][0] *= cr0; o[nt][1] *= cr0;
            o[nt][2] *= cr1; o[nt][3] *= cr1;
        }
        __syncwarp();

        // ---- O += P V (16 x 128 per warp) ----
        #pragma unroll
        for (int kt = 0; kt < 4; kt++) {
            uint4 af = *(const uint4*)(Ps + (wid*4 + kt)*128 + lane*4);
            #pragma unroll
            for (int nt = 0; nt < 16; nt++) {
                uint2 bf = *(const uint2*)(Vs + (nt*4 + kt)*64 + lane*2);
                mma_f16(o[nt], af, bf);
            }
        }
    }

    // ---- output ----
    float inv0 = 1.f / l0, inv1 = 1.f / l1;
    const int row_lo = q0 + wid*16 + (lane >> 2);
    const int row_hi = row_lo + 8;
    float* oplo = Ob + ((size_t)b*S_LEN + row_lo)*D_MODEL + h*HD;
    float* ophi = Ob + ((size_t)b*S_LEN + row_hi)*D_MODEL + h*HD;
    #pragma unroll
    for (int nt = 0; nt < 16; nt++) {
        int d0 = nt*8 + (lane & 3)*2;
        float2 vlo; vlo.x = o[nt][0]*inv0; vlo.y = o[nt][1]*inv0;
        float2 vhi; vhi.x = o[nt][2]*inv1; vhi.y = o[nt][3]*inv1;
        *(float2*)(oplo + d0) = vlo;
        *(float2*)(ophi + d0) = vhi;
    }
}

extern "C" void kernel_launch(void* const* d_in, const int* in_sizes, int n_in,
                              void* d_out, int out_size)
{
    const float* x    = (const float*)d_in[0];
    const float* fcos = (const float*)d_in[1];
    const float* fsin = (const float*)d_in[2];
    const float* wq   = (const float*)d_in[3];
    const float* wk   = (const float*)d_in[4];
    const float* wv   = (const float*)d_in[5];
    const float* wo   = (const float*)d_in[6];
    float* out = (float*)d_out;

    float *pQ, *pK, *pV, *pO;
    cudaGetSymbolAddress((void**)&pQ, g_Q);
    cudaGetSymbolAddress((void**)&pK, g_K);
    cudaGetSymbolAddress((void**)&pV, g_V);
    cudaGetSymbolAddress((void**)&pO, g_O);

    cudaFuncSetAttribute(attn_tc, cudaFuncAttributeMaxDynamicSharedMemorySize, AT_SMEM);

    // fused QKV projections (+rope, scatter) : grid x covers 2048 | 512 | 512 cols
    gemm_f16<3><<<dim3((D_MODEL + 2*NKVH*HD)/128, MROWS/128), 256, G_SMEM>>>(
        x, wq, wk, wv, pQ, pK, pV, fcos, fsin);
    // attention -> g_O [b,s,h*d]
    attn_tc<<<dim3(S_LEN/64, B_SZ*NH), 128, AT_SMEM>>>(pQ, pK, pV, pO);
    // output projection -> d_out
    gemm_f16<0><<<dim3(D_MODEL/128, MROWS/128), 256, G_SMEM>>>(
        pO, wo, nullptr, nullptr, out, nullptr, nullptr, nullptr, nullptr);
}

// round 9
// speedup vs baseline: 8.5705x; 1.9129x over previous
#include <cuda_runtime.h>
#include <cuda_fp16.h>
#include <cstdint>
#include <math.h>

#define B_SZ 2
#define S_LEN 2048
#define D_MODEL 2048
#define NH 16
#define NKVH 4
#define HD 128
#define MROWS (B_SZ*S_LEN)

// fp16 scratch (allocation-free rule: __device__ globals)
__device__ __half g_Xh[(size_t)MROWS*D_MODEL];
__device__ __half g_Wqkv[(size_t)3072*D_MODEL];     // wq(2048) | wk(512) | wv(512) rows
__device__ __half g_Woh[(size_t)D_MODEL*D_MODEL];
__device__ __half g_Qh[(size_t)B_SZ*NH*S_LEN*HD];   // [b,h,s,d] post-rope
__device__ __half g_Kh[(size_t)B_SZ*NKVH*S_LEN*HD];
__device__ __half g_Vh[(size_t)B_SZ*NKVH*S_LEN*HD];
__device__ __half g_Oh[(size_t)B_SZ*S_LEN*D_MODEL]; // [b,s,h*d]

__device__ __forceinline__ void mma_f16(float* c, const uint4& a, const uint2& b){
    asm volatile("mma.sync.aligned.m16n8k16.row.col.f32.f16.f16.f32 "
        "{%0,%1,%2,%3}, {%4,%5,%6,%7}, {%8,%9}, {%0,%1,%2,%3};"
        : "+f"(c[0]), "+f"(c[1]), "+f"(c[2]), "+f"(c[3])
        : "r"(a.x), "r"(a.y), "r"(a.z), "r"(a.w), "r"(b.x), "r"(b.y));
}
#define LDSM4(v, addr) asm volatile( \
    "ldmatrix.sync.aligned.m8n8.x4.shared.b16 {%0,%1,%2,%3}, [%4];" \
    : "=r"((v).x), "=r"((v).y), "=r"((v).z), "=r"((v).w) : "r"(addr))
#define LDSM4T(v, addr) asm volatile( \
    "ldmatrix.sync.aligned.m8n8.x4.trans.shared.b16 {%0,%1,%2,%3}, [%4];" \
    : "=r"((v).x), "=r"((v).y), "=r"((v).z), "=r"((v).w) : "r"(addr))
#define CP16(dst, src) asm volatile( \
    "cp.async.cg.shared.global [%0], [%1], 16;" :: "r"(dst), "l"(src))
#define CPCOMMIT asm volatile("cp.async.commit_group;")
#define CPWAIT(n) asm volatile("cp.async.wait_group %0;" :: "n"(n))

// ---------------- fp32 -> fp16 conversion prepass ----------------
__global__ void cvt_h(const float* __restrict__ s, __half* __restrict__ d, int n4){
    int i = blockIdx.x*256 + threadIdx.x;
    if (i < n4){
        float4 f = ((const float4*)s)[i];
        __half2 h0 = __floats2half2_rn(f.x, f.y);
        __half2 h1 = __floats2half2_rn(f.z, f.w);
        ((__half2*)d)[2*i]   = h0;
        ((__half2*)d)[2*i+1] = h1;
    }
}

// ============ GEMM: C = A * W^T (fp16 in, cp.async + ldmatrix) ============
// BM=BN=128, BK=64, 3 stages, 128 threads (4 warps, 64x64 each).
// MODE 0: C f32 row-major [M,2048].  MODE 3: fused QKV -> fp16 [b,h,s,d] + rope.
#define GEMM_SMEM (6*16384)

template<int MODE>
__global__ void __launch_bounds__(128) gemm_h(
    const __half* __restrict__ A, const __half* __restrict__ Bw,
    float* __restrict__ Cf,
    const float* __restrict__ fcos, const float* __restrict__ fsin)
{
    extern __shared__ char sm[];
    const uint32_t sb = (uint32_t)__cvta_generic_to_shared(sm);
    const int tid = threadIdx.x, lane = tid & 31, wid = tid >> 5;
    const int wm = wid & 1, wn = wid >> 1;
    const int m0 = blockIdx.y * 128;
    const int n0g = blockIdx.x * 128;

    __half* Ch = nullptr; int n0 = n0g, Hn = 0, rope = 0;
    if (MODE == 3) {
        if (n0g < 2048)      { Ch = g_Qh; n0 = n0g;        Hn = NH;   rope = 1; }
        else if (n0g < 2560) { Ch = g_Kh; n0 = n0g - 2048; Hn = NKVH; rope = 1; }
        else                 { Ch = g_Vh; n0 = n0g - 2560; Hn = NKVH; rope = 0; }
    }
    const __half* Ag0 = A  + (size_t)m0  * D_MODEL;
    const __half* Bg0 = Bw + (size_t)n0g * D_MODEL;

    auto loadStage = [&](int s, int kc){
        uint32_t ab = sb + s*16384;
        uint32_t bb = sb + 49152 + s*16384;
        const __half* Ag = Ag0 + kc;
        const __half* Bg = Bg0 + kc;
        #pragma unroll
        for (int i = 0; i < 8; i++){
            int idx = tid + 128*i;
            int r = idx >> 3, c = idx & 7;
            CP16(ab + r*128 + ((c ^ (r & 7)) << 4), Ag + (size_t)r*D_MODEL + c*8);
        }
        #pragma unroll
        for (int i = 0; i < 8; i++){
            int idx = tid + 128*i;
            int r = idx >> 3, c = idx & 7;
            CP16(bb + r*128 + ((c ^ (r & 7)) << 4), Bg + (size_t)r*D_MODEL + c*8);
        }
        CPCOMMIT;
    };

    float acc[4][8][4];
    #pragma unroll
    for (int mt = 0; mt < 4; mt++)
        #pragma unroll
        for (int n = 0; n < 8; n++)
            #pragma unroll
            for (int r = 0; r < 4; r++) acc[mt][n][r] = 0.f;

    loadStage(0, 0);
    loadStage(1, 64);

    for (int i = 0; i < 32; i++){
        if (i < 31) { CPWAIT(1); } else { CPWAIT(0); }
        __syncthreads();
        if (i + 2 < 32) loadStage((i+2)%3, (i+2)*64);

        const uint32_t ab = sb + (i%3)*16384;
        const uint32_t bb = sb + 49152 + (i%3)*16384;
        #pragma unroll
        for (int kt = 0; kt < 4; kt++){
            uint4 af[4];
            #pragma unroll
            for (int mt = 0; mt < 4; mt++){
                int r = wm*64 + mt*16 + (lane & 15);
                int c = kt*2 + (lane >> 4);
                LDSM4(af[mt], ab + r*128 + ((c ^ (r & 7)) << 4));
            }
            #pragma unroll
            for (int p = 0; p < 4; p++){
                int r = wn*64 + p*16 + ((lane >> 4) << 3) + (lane & 7);
                int c = kt*2 + ((lane >> 3) & 1);
                uint4 bq;
                LDSM4(bq, bb + r*128 + ((c ^ (r & 7)) << 4));
                uint2 b0 = make_uint2(bq.x, bq.y);
                uint2 b1 = make_uint2(bq.z, bq.w);
                #pragma unroll
                for (int mt = 0; mt < 4; mt++){
                    mma_f16(acc[mt][2*p],   af[mt], b0);
                    mma_f16(acc[mt][2*p+1], af[mt], b1);
                }
            }
        }
    }

    // -------- epilogue --------
    const int l4 = lane >> 2;
    const int l2 = (lane & 3) * 2;
    #pragma unroll
    for (int mt = 0; mt < 4; mt++){
        #pragma unroll
        for (int n = 0; n < 8; n++){
            const int col = (MODE == 0 ? n0g : n0) + wn*64 + n*8 + l2;
            #pragma unroll
            for (int half = 0; half < 2; half++){
                const int row = m0 + wm*64 + mt*16 + l4 + half*8;
                float xr = acc[mt][n][half*2 + 0];
                float xi = acc[mt][n][half*2 + 1];
                if (MODE == 0){
                    float2 o; o.x = xr; o.y = xi;
                    *(float2*)(Cf + (size_t)row*D_MODEL + col) = o;
                } else {
                    const int b = row >> 11;
                    const int s = row & (S_LEN-1);
                    const int h = col >> 7;
                    const int d = col & (HD-1);
                    __half* op = Ch + (((size_t)(b*Hn + h))*S_LEN + s)*HD + d;
                    if (rope){
                        float cs = fcos[s*(HD/2) + (d>>1)];
                        float sn = fsin[s*(HD/2) + (d>>1)];
                        *(__half2*)op = __floats2half2_rn(xr*cs - xi*sn, xr*sn + xi*cs);
                    } else {
                        *(__half2*)op = __floats2half2_rn(xr, xi);
                    }
                }
            }
        }
    }
}

// ===== Flash attention v2: fp16, BQ=128, BKT=64, cp.async dbuf, ldmatrix =====
// smem: Q 32KB | K[2] 2x16KB | V[2] 2x16KB | P 16KB  = 112KB
#define ATT_SMEM 114688

__global__ void __launch_bounds__(256) attn2()
{
    extern __shared__ char sm[];
    const uint32_t sb = (uint32_t)__cvta_generic_to_shared(sm);
    const uint32_t Qb = sb;
    const uint32_t Kb0 = sb + 32768, Kb1 = sb + 49152;
    const uint32_t Vb0 = sb + 65536, Vb1 = sb + 81920;
    uint32_t* Ps = (uint32_t*)(sm + 98304);   // [8 mt][4 kt][128] words

    const int tid = threadIdx.x, lane = tid & 31, wid = tid >> 5;
    const int bz  = blockIdx.y >> 4;
    const int hh  = blockIdx.y & 15;
    const int kvh = hh >> 2;
    const int qt  = blockIdx.x;
    const int q0  = qt * 128;

    const __half* Qg = g_Qh + ((size_t)(bz*NH   + hh )*S_LEN + q0)*HD;
    const __half* Kg = g_Kh + ((size_t)(bz*NKVH + kvh)*S_LEN)*HD;
    const __half* Vg = g_Vh + ((size_t)(bz*NKVH + kvh)*S_LEN)*HD;

    auto loadKV = [&](int buf, int k0){
        uint32_t kb = buf ? Kb1 : Kb0;
        uint32_t vb = buf ? Vb1 : Vb0;
        #pragma unroll
        for (int i = 0; i < 4; i++){
            int idx = tid + 256*i;
            int r = idx >> 4, c = idx & 15;
            uint32_t off = r*256 + ((c ^ (r & 7)) << 4);
            CP16(kb + off, Kg + (size_t)(k0 + r)*HD + c*8);
            CP16(vb + off, Vg + (size_t)(k0 + r)*HD + c*8);
        }
        CPCOMMIT;
    };

    // group 0: Q + KV(0)
    #pragma unroll
    for (int i = 0; i < 8; i++){
        int idx = tid + 256*i;
        int r = idx >> 4, c = idx & 15;
        CP16(Qb + r*256 + ((c ^ (r & 7)) << 4), Qg + (size_t)r*HD + c*8);
    }
    loadKV(0, 0);

    const int nkt = 2*qt + 2;
    const float scale = 0.08838834764831845f;   // 1/sqrt(128)
    const int qlo = q0 + wid*16 + (lane >> 2);
    const int qhi = qlo + 8;
    const int diagTile = 2*qt + (wid >= 4 ? 1 : 0);

    uint4 qf[8];
    float m0 = -1e30f, m1 = -1e30f, l0 = 0.f, l1 = 0.f;
    float o[16][4];
    #pragma unroll
    for (int nt = 0; nt < 16; nt++)
        #pragma unroll
        for (int r = 0; r < 4; r++) o[nt][r] = 0.f;

    for (int tile = 0; tile < nkt; tile++){
        if (tile + 1 < nkt) { loadKV((tile+1) & 1, (tile+1)*64); CPWAIT(1); }
        else                { CPWAIT(0); }
        __syncthreads();

        if (tile == 0){
            #pragma unroll
            for (int kt = 0; kt < 8; kt++){
                int r = wid*16 + (lane & 15);
                int c = kt*2 + (lane >> 4);
                LDSM4(qf[kt], Qb + r*256 + ((c ^ (r & 7)) << 4));
            }
        }

        const int k0 = tile * 64;
        const bool skip = (tile == 2*qt + 1) && (wid < 4);
        if (!skip){
            const uint32_t kb = (tile & 1) ? Kb1 : Kb0;
            const uint32_t vb = (tile & 1) ? Vb1 : Vb0;

            // ---- S = Q K^T (16 x 64 per warp) ----
            float sacc[8][4];
            #pragma unroll
            for (int n = 0; n < 8; n++)
                #pragma unroll
                for (int r = 0; r < 4; r++) sacc[n][r] = 0.f;
            #pragma unroll
            for (int kt = 0; kt < 8; kt++){
                #pragma unroll
                for (int p = 0; p < 4; p++){
                    int r = p*16 + ((lane >> 4) << 3) + (lane & 7);
                    int c = kt*2 + ((lane >> 3) & 1);
                    uint4 bq;
                    LDSM4(bq, kb + r*256 + ((c ^ (r & 7)) << 4));
                    mma_f16(sacc[2*p],   qf[kt], make_uint2(bq.x, bq.y));
                    mma_f16(sacc[2*p+1], qf[kt], make_uint2(bq.z, bq.w));
                }
            }

            // ---- online softmax ----
            const bool diag = (tile == diagTile);
            float mx0 = -1e30f, mx1 = -1e30f;
            #pragma unroll
            for (int n = 0; n < 8; n++){
                float v0 = sacc[n][0]*scale, v1 = sacc[n][1]*scale;
                float v2 = sacc[n][2]*scale, v3 = sacc[n][3]*scale;
                if (diag){
                    int c0 = k0 + n*8 + (lane & 3)*2;
                    if (c0     > qlo) v0 = -1e30f;
                    if (c0 + 1 > qlo) v1 = -1e30f;
                    if (c0     > qhi) v2 = -1e30f;
                    if (c0 + 1 > qhi) v3 = -1e30f;
                }
                sacc[n][0]=v0; sacc[n][1]=v1; sacc[n][2]=v2; sacc[n][3]=v3;
                mx0 = fmaxf(mx0, fmaxf(v0, v1));
                mx1 = fmaxf(mx1, fmaxf(v2, v3));
            }
            mx0 = fmaxf(mx0, __shfl_xor_sync(0xffffffffu, mx0, 1));
            mx0 = fmaxf(mx0, __shfl_xor_sync(0xffffffffu, mx0, 2));
            mx1 = fmaxf(mx1, __shfl_xor_sync(0xffffffffu, mx1, 1));
            mx1 = fmaxf(mx1, __shfl_xor_sync(0xffffffffu, mx1, 2));
            float nm0 = fmaxf(m0, mx0), nm1 = fmaxf(m1, mx1);
            float cr0 = __expf(m0 - nm0), cr1 = __expf(m1 - nm1);
            m0 = nm0; m1 = nm1;

            float s0 = 0.f, s1 = 0.f;
            #pragma unroll
            for (int n = 0; n < 8; n++){
                float p0 = __expf(sacc[n][0] - nm0);
                float p1 = __expf(sacc[n][1] - nm0);
                float p2 = __expf(sacc[n][2] - nm1);
                float p3 = __expf(sacc[n][3] - nm1);
                s0 += p0 + p1; s1 += p2 + p3;
                __half2 w0 = __floats2half2_rn(p0, p1);
                __half2 w1 = __floats2half2_rn(p2, p3);
                uint2 w; w.x = *(uint32_t*)&w0; w.y = *(uint32_t*)&w1;
                *(uint2*)(Ps + (wid*4 + (n>>1))*128 + (lane>>2)*16 + (lane&3)*4 + 2*(n&1)) = w;
            }
            s0 += __shfl_xor_sync(0xffffffffu, s0, 1);
            s0 += __shfl_xor_sync(0xffffffffu, s0, 2);
            s1 += __shfl_xor_sync(0xffffffffu, s1, 1);
            s1 += __shfl_xor_sync(0xffffffffu, s1, 2);
            l0 = l0*cr0 + s0;
            l1 = l1*cr1 + s1;
            #pragma unroll
            for (int nt = 0; nt < 16; nt++){
                o[nt][0] *= cr0; o[nt][1] *= cr0;
                o[nt][2] *= cr1; o[nt][3] *= cr1;
            }
            __syncwarp();

            // ---- O += P V (16 x 128 per warp) ----
            #pragma unroll
            for (int kt = 0; kt < 4; kt++){
                uint4 pf = *(const uint4*)(Ps + (wid*4 + kt)*128 + lane*4);
                #pragma unroll
                for (int p = 0; p < 8; p++){
                    int r = kt*16 + ((lane >> 3) & 1)*8 + (lane & 7);
                    int c = 2*p + (lane >> 4);
                    uint4 bq;
                    LDSM4T(bq, vb + r*256 + ((c ^ (r & 7)) << 4));
                    mma_f16(o[2*p],   pf, make_uint2(bq.x, bq.y));
                    mma_f16(o[2*p+1], pf, make_uint2(bq.z, bq.w));
                }
            }
        }
        __syncthreads();
    }

    // ---- output (fp16) ----
    float inv0 = 1.f / l0, inv1 = 1.f / l1;
    const int row_lo = q0 + wid*16 + (lane >> 2);
    const int row_hi = row_lo + 8;
    __half* olo = g_Oh + ((size_t)bz*S_LEN + row_lo)*D_MODEL + hh*HD;
    __half* ohi = g_Oh + ((size_t)bz*S_LEN + row_hi)*D_MODEL + hh*HD;
    #pragma unroll
    for (int nt = 0; nt < 16; nt++){
        int d0 = nt*8 + (lane & 3)*2;
        *(__half2*)(olo + d0) = __floats2half2_rn(o[nt][0]*inv0, o[nt][1]*inv0);
        *(__half2*)(ohi + d0) = __floats2half2_rn(o[nt][2]*inv1, o[nt][3]*inv1);
    }
}

extern "C" void kernel_launch(void* const* d_in, const int* in_sizes, int n_in,
                              void* d_out, int out_size)
{
    const float* x    = (const float*)d_in[0];
    const float* fcos = (const float*)d_in[1];
    const float* fsin = (const float*)d_in[2];
    const float* wq   = (const float*)d_in[3];
    const float* wk   = (const float*)d_in[4];
    const float* wv   = (const float*)d_in[5];
    const float* wo   = (const float*)d_in[6];
    float* out = (float*)d_out;

    __half *pXh, *pWqkv, *pWoh, *pOh;
    cudaGetSymbolAddress((void**)&pXh,  g_Xh);
    cudaGetSymbolAddress((void**)&pWqkv, g_Wqkv);
    cudaGetSymbolAddress((void**)&pWoh, g_Woh);
    cudaGetSymbolAddress((void**)&pOh,  g_Oh);

    cudaFuncSetAttribute(gemm_h<3>, cudaFuncAttributeMaxDynamicSharedMemorySize, GEMM_SMEM);
    cudaFuncSetAttribute(gemm_h<0>, cudaFuncAttributeMaxDynamicSharedMemorySize, GEMM_SMEM);
    cudaFuncSetAttribute(attn2, cudaFuncAttributeMaxDynamicSharedMemorySize, ATT_SMEM);

    // fp32 -> fp16 prepass
    cvt_h<<<(MROWS*D_MODEL/4 + 255)/256, 256>>>(x,  pXh, MROWS*D_MODEL/4);
    cvt_h<<<(2048*2048/4 + 255)/256, 256>>>(wq, pWqkv,                    2048*2048/4);
    cvt_h<<<( 512*2048/4 + 255)/256, 256>>>(wk, pWqkv + (size_t)2048*2048, 512*2048/4);
    cvt_h<<<( 512*2048/4 + 255)/256, 256>>>(wv, pWqkv + (size_t)2560*2048, 512*2048/4);
    cvt_h<<<(2048*2048/4 + 255)/256, 256>>>(wo, pWoh,                     2048*2048/4);

    // fused QKV projection (+rope, scatter to [b,h,s,d] fp16)
    gemm_h<3><<<dim3(3072/128, MROWS/128), 128, GEMM_SMEM>>>(pXh, pWqkv, nullptr, fcos, fsin);
    // attention -> g_Oh [b,s,h*d] fp16
    attn2<<<dim3(S_LEN/128, B_SZ*NH), 256, ATT_SMEM>>>();
    // output projection -> d_out (f32)
    gemm_h<0><<<dim3(D_MODEL/128, MROWS/128), 128, GEMM_SMEM>>>(pOh, pWoh, out, nullptr, nullptr);
}